// round 12
// baseline (speedup 1.0000x reference)
#include <cuda_runtime.h>

// out = clamp(floor(x * 16 + r) * (1/16), -8.0, 7.9375)
// WL=8, FL=4 -> sigma = 2^-4 (power of 2: *16 and *0.0625 are exact in fp32).
//
// HBM-roofline streaming kernel (~90% of 8 TB/s). Measured: cache hints
// neutral, global-split MLP batching slightly negative, block=512 best.
// This round: block-LOCAL x2 unroll — each CTA covers a contiguous
// 2*512 float4 window, thread t handles base+t and base+t+512. Both load
// sweeps coalesced + adjacent (same L2/TLB pages), MLP_p1 = 4.

__device__ __forceinline__ float quant1(float x, float r) {
    float q = floorf(fmaf(x, 16.0f, r)) * 0.0625f;
    q = fminf(q, 7.9375f);
    q = fmaxf(q, -8.0f);
    return q;
}

__device__ __forceinline__ float4 quant4(float4 xv, float4 rv) {
    float4 o;
    o.x = quant1(xv.x, rv.x);
    o.y = quant1(xv.y, rv.y);
    o.z = quant1(xv.z, rv.z);
    o.w = quant1(xv.w, rv.w);
    return o;
}

__global__ void __launch_bounds__(512) quant_kernel_v4x2(
    const float4* __restrict__ x,
    const float4* __restrict__ r,
    float4* __restrict__ out,
    int n4)
{
    int i0 = blockIdx.x * (blockDim.x * 2) + threadIdx.x;
    int i1 = i0 + blockDim.x;
    if (i1 < n4) {
        // Common case: both in range. Front-batch all 4 loads.
        float4 x0 = x[i0];
        float4 r0 = r[i0];
        float4 x1 = x[i1];
        float4 r1 = r[i1];
        out[i0] = quant4(x0, r0);
        out[i1] = quant4(x1, r1);
    } else if (i0 < n4) {
        out[i0] = quant4(x[i0], r[i0]);
    }
}

__global__ void quant_kernel_tail(
    const float* __restrict__ x,
    const float* __restrict__ r,
    float* __restrict__ out,
    int start, int n)
{
    int i = start + blockIdx.x * blockDim.x + threadIdx.x;
    if (i < n) out[i] = quant1(x[i], r[i]);
}

extern "C" void kernel_launch(void* const* d_in, const int* in_sizes, int n_in,
                              void* d_out, int out_size) {
    const float* x = (const float*)d_in[0];
    const float* r = (const float*)d_in[1];
    float* out = (float*)d_out;
    int n = in_sizes[0];

    int n4 = n / 4;
    if (n4 > 0) {
        const int threads = 512;
        const int per_block = threads * 2;
        int blocks = (n4 + per_block - 1) / per_block;  // 32768 for n=2^27
        quant_kernel_v4x2<<<blocks, threads>>>(
            (const float4*)x, (const float4*)r, (float4*)out, n4);
    }
    int rem_start = n4 * 4;
    int rem = n - rem_start;
    if (rem > 0) {
        quant_kernel_tail<<<(rem + 255) / 256, 256>>>(x, r, out, rem_start, n);
    }
}

// round 14
// speedup vs baseline: 1.0147x; 1.0147x over previous
#include <cuda_runtime.h>

// out = clamp(floor(x * 16 + r) * (1/16), -8.0, 7.9375)
// WL=8, FL=4 -> sigma = 2^-4 (power of 2: *16 and *0.0625 are exact in fp32).
//
// FINAL converged HBM-roofline kernel: ~7.2 TB/s (90% of 8 TB/s spec),
// DRAM-pct 90.6, all compute pipes idle. Exhaustive knob history:
//   - single linear float4 stream beats split/unrolled streams (R2, R12)
//   - cache hints (__ldcs/__stcs) neutral (R6)
//   - block 512 marginally beats 256 (R10: dur_us 225.5, best measured)
//   - MLP batching neutral/negative in both global and block-local forms
// Traffic is mandatory (2 reads + 1 write x 512 MB fp32); nothing left to cut.
// (R13 was a container infra failure; this is the R10 winner resubmitted.)

__device__ __forceinline__ float quant1(float x, float r) {
    float q = floorf(fmaf(x, 16.0f, r)) * 0.0625f;
    q = fminf(q, 7.9375f);
    q = fmaxf(q, -8.0f);
    return q;
}

__global__ void __launch_bounds__(512) quant_kernel_v4(
    const float4* __restrict__ x,
    const float4* __restrict__ r,
    float4* __restrict__ out,
    int n4)
{
    int i = blockIdx.x * blockDim.x + threadIdx.x;
    if (i < n4) {
        float4 xv = x[i];
        float4 rv = r[i];
        float4 o;
        o.x = quant1(xv.x, rv.x);
        o.y = quant1(xv.y, rv.y);
        o.z = quant1(xv.z, rv.z);
        o.w = quant1(xv.w, rv.w);
        out[i] = o;
    }
}

__global__ void quant_kernel_tail(
    const float* __restrict__ x,
    const float* __restrict__ r,
    float* __restrict__ out,
    int start, int n)
{
    int i = start + blockIdx.x * blockDim.x + threadIdx.x;
    if (i < n) out[i] = quant1(x[i], r[i]);
}

extern "C" void kernel_launch(void* const* d_in, const int* in_sizes, int n_in,
                              void* d_out, int out_size) {
    const float* x = (const float*)d_in[0];
    const float* r = (const float*)d_in[1];
    float* out = (float*)d_out;
    int n = in_sizes[0];

    int n4 = n / 4;
    if (n4 > 0) {
        const int threads = 512;
        int blocks = (n4 + threads - 1) / threads;  // exact: 65536 for n=2^27
        quant_kernel_v4<<<blocks, threads>>>(
            (const float4*)x, (const float4*)r, (float4*)out, n4);
    }
    int rem_start = n4 * 4;
    int rem = n - rem_start;
    if (rem > 0) {
        quant_kernel_tail<<<(rem + 255) / 256, 256>>>(x, r, out, rem_start, n);
    }
}